// round 9
// baseline (speedup 1.0000x reference)
#include <cuda_runtime.h>
#include <math.h>
#include <stdint.h>

// ---------------------------------------------------------------------------
// QuickPatternMatchingLoss
//   out[b] = log( (1/ls) * sum_{l: mask} sum_o ss_hmm[o,l] *
//                 softmax_o( W[:, :20] . x[b,1:,l] + slog[:,l] ) )
//   slog[o,l] = b[o] + sum_h W[o,20+h] * seq_hmm[h,l]
//   mask[b,l] = ( max_{c>=1} x[b,c,l] > x[b,0,l] )
//
// R9: persistent double-buffered TMA (R8 skeleton, proven), but 512 threads
// per CTA, ONE column per thread. R8 was compute-phase-bound at occ=12.6%
// (2 warps/SMSP exposed every latency: mbar wake, LDS, shfl chain, BAR).
// 16 warps/CTA -> 32 warps/SM hides it all; softmax rebased on logit0
// (e0==1, one less MUFU); per-thread tables = 5 regs; 1 barrier per row
// (parity-indexed reduce scratch).
// ---------------------------------------------------------------------------

#define MAX_L 2048
__device__ float g_slog[3 * MAX_L];   // fallback path scratch

#define FL 512
#define FC 21
#define ROW_BYTES (FC * FL * 4)        // 43008
#define GRIDP 304                      // 2 CTAs/SM x 152 SMs
#define SMEM_DYN (2 * ROW_BYTES)       // 86016
#define NT 512                         // threads per CTA (fast path)

__device__ __forceinline__ uint32_t smem_u32(const void* p) {
    uint32_t a;
    asm("{ .reg .u64 t; cvta.to.shared.u64 t, %1; cvt.u32.u64 %0, t; }"
        : "=r"(a) : "l"(p));
    return a;
}
__device__ __forceinline__ void mbar_init(uint32_t mbar, uint32_t count) {
    asm volatile("mbarrier.init.shared.b64 [%0], %1;" :: "r"(mbar), "r"(count) : "memory");
}
__device__ __forceinline__ void mbar_expect_tx(uint32_t mbar, uint32_t bytes) {
    asm volatile("mbarrier.arrive.expect_tx.shared.b64 _, [%0], %1;"
                 :: "r"(mbar), "r"(bytes) : "memory");
}
__device__ __forceinline__ void bulk_g2s(uint32_t dst, const void* src,
                                         uint32_t bytes, uint32_t mbar) {
    asm volatile(
        "cp.async.bulk.shared::cta.global.mbarrier::complete_tx::bytes "
        "[%0], [%1], %2, [%3];"
        :: "r"(dst), "l"(src), "r"(bytes), "r"(mbar) : "memory");
}
__device__ __forceinline__ void mbar_wait(uint32_t mbar, uint32_t parity) {
    uint32_t done;
    asm volatile(
        "{\n\t.reg .pred p;\n\t"
        "mbarrier.try_wait.parity.acquire.cta.shared::cta.b64 p, [%1], %2;\n\t"
        "selp.b32 %0, 1, 0, p;\n\t}"
        : "=r"(done) : "r"(mbar), "r"(parity) : "memory");
    if (!done) {
        asm volatile(
            "{\n\t.reg .pred P1;\n\t"
            "WAIT_LOOP_%=:\n\t"
            "mbarrier.try_wait.parity.acquire.cta.shared::cta.b64 P1, [%0], %1, 0x989680;\n\t"
            "@P1 bra.uni WAIT_DONE_%=;\n\t"
            "bra.uni WAIT_LOOP_%=;\n\t"
            "WAIT_DONE_%=:\n\t}"
            :: "r"(mbar), "r"(parity) : "memory");
    }
}

// ---- persistent double-buffered fast path -----------------------------------
__global__ void __launch_bounds__(NT, 2)
qpml_persist(const float* __restrict__ x,
             const float* __restrict__ seq_hmm,
             const float* __restrict__ ss_hmm,
             const float* __restrict__ W,
             const float* __restrict__ bvec,
             float* __restrict__ out,
             int B, int H, int wstride)
{
    extern __shared__ __align__(16) float dyn[];
    float* buf[2] = { dyn, dyn + FC * FL };

    __shared__ float sW0[64], sW1[64], sW2[64];
    __shared__ __align__(8) unsigned long long mb[2];
    __shared__ float rs0[2][16], rs1[2][16];

    const int t = threadIdx.x;
    const int warp = t >> 5, lane = t & 31;
    const int cta = blockIdx.x;
    const int G = gridDim.x;

    if (t < 2) mbar_init(smem_u32(&mb[t]), 1);
    if (t < wstride && t < 64) {
        sW0[t] = __ldg(&W[0 * wstride + t]);
        sW1[t] = __ldg(&W[1 * wstride + t]);
        sW2[t] = __ldg(&W[2 * wstride + t]);
    }
    __syncthreads();

    const uint32_t buf_sm[2] = { smem_u32(buf[0]), smem_u32(buf[1]) };
    const uint32_t mbs[2]    = { smem_u32(&mb[0]), smem_u32(&mb[1]) };

    // prefill both buffers
    if (t == 0) {
        if (cta < B) {
            mbar_expect_tx(mbs[0], ROW_BYTES);
            bulk_g2s(buf_sm[0], (const char*)x + (size_t)cta * ROW_BYTES,
                     ROW_BYTES, mbs[0]);
        }
        if (cta + G < B) {
            mbar_expect_tx(mbs[1], ROW_BYTES);
            bulk_g2s(buf_sm[1], (const char*)x + (size_t)(cta + G) * ROW_BYTES,
                     ROW_BYTES, mbs[1]);
        }
    }

    // per-thread tables for column t (computed under the first fill):
    // d10 = slog1-slog0, d20 = slog2-slog0, h0,h1,h2  -> 5 registers
    float d10, d20, h0c, h1c, h2c;
    {
        float s0 = __ldg(&bvec[0]), s1 = __ldg(&bvec[1]), s2 = __ldg(&bvec[2]);
        for (int h = 0; h < H; ++h) {
            float v = __ldg(&seq_hmm[h * FL + t]);
            s0 = fmaf(sW0[20 + h], v, s0);
            s1 = fmaf(sW1[20 + h], v, s1);
            s2 = fmaf(sW2[20 + h], v, s2);
        }
        d10 = s1 - s0;
        d20 = s2 - s0;
        h0c = __ldg(&ss_hmm[0 * FL + t]);
        h1c = __ldg(&ss_hmm[1 * FL + t]);
        h2c = __ldg(&ss_hmm[2 * FL + t]);
    }

    int ph[2] = {0, 0};
    int it = 0;
    for (int r = cta; r < B; r += G, ++it) {
        const int k = it & 1;
        const int p = it & 1;          // reduce-scratch parity
        const float* bk = buf[k];

        mbar_wait(mbs[k], ph[k]);
        ph[k] ^= 1;

        // column t of this row
        float x0 = bk[t];                   // gap channel
        float mx = -INFINITY;
        float a0 = 0.f, a1 = 0.f, a2 = 0.f;
        #pragma unroll
        for (int c = 1; c < FC; ++c) {
            float v = bk[c * FL + t];
            mx = fmaxf(mx, v);
            a0 = fmaf(sW0[c - 1], v, a0);
            a1 = fmaf(sW1[c - 1], v, a1);
            a2 = fmaf(sW2[c - 1], v, a2);
        }
        // softmax rebased on logit0: e0 == 1
        float e1 = __expf((a1 - a0) + d10);
        float e2 = __expf((a2 - a0) + d20);
        float num = fmaf(h2c, e2, fmaf(h1c, e1, h0c));
        float den = 1.f + e1 + e2;
        bool m = mx > x0;
        float contrib = m ? __fdividef(num, den) : 0.f;
        float cnt     = m ? 1.f : 0.f;

        #pragma unroll
        for (int off = 16; off > 0; off >>= 1) {
            contrib += __shfl_down_sync(0xffffffffu, contrib, off);
            cnt     += __shfl_down_sync(0xffffffffu, cnt, off);
        }
        if (lane == 0) { rs0[p][warp] = contrib; rs1[p][warp] = cnt; }

        __syncthreads();   // rs visible to warp0 AND all reads of buf[k] done

        if (warp == 0) {
            float s = (lane < 16) ? rs0[p][lane] : 0.f;
            float c = (lane < 16) ? rs1[p][lane] : 0.f;
            #pragma unroll
            for (int off = 8; off > 0; off >>= 1) {
                s += __shfl_down_sync(0xffffffffu, s, off);
                c += __shfl_down_sync(0xffffffffu, c, off);
            }
            if (lane == 0) {
                out[r] = logf(s / c);
                int rf = r + 2 * G;
                if (rf < B) {
                    mbar_expect_tx(mbs[k], ROW_BYTES);
                    bulk_g2s(buf_sm[k],
                             (const char*)x + (size_t)rf * ROW_BYTES,
                             ROW_BYTES, mbs[k]);
                }
            }
        }
        // no second barrier: next row uses the other rs parity and waits on
        // the other buffer's mbar; refill of buf[k] is ordered after the
        // barrier above (all reads of buf[k] complete).
    }
}

// ---- fallback paths (non-512x21 shapes) --------------------------------------
__global__ void slog_kernel(const float* __restrict__ seq_hmm,
                            const float* __restrict__ W,
                            const float* __restrict__ bvec,
                            int L, int H, int wstride)
{
    int l = blockIdx.x * blockDim.x + threadIdx.x;
    if (l >= L) return;
    float s0 = bvec[0], s1 = bvec[1], s2 = bvec[2];
    for (int h = 0; h < H; ++h) {
        float v = __ldg(&seq_hmm[h * L + l]);
        s0 = fmaf(__ldg(&W[0 * wstride + 20 + h]), v, s0);
        s1 = fmaf(__ldg(&W[1 * wstride + 20 + h]), v, s1);
        s2 = fmaf(__ldg(&W[2 * wstride + 20 + h]), v, s2);
    }
    g_slog[0 * L + l] = s0;
    g_slog[1 * L + l] = s1;
    g_slog[2 * L + l] = s2;
}

__global__ void __launch_bounds__(128, 6)
qpml_generic(const float* __restrict__ x,
             const float* __restrict__ ss_hmm,
             const float* __restrict__ W,
             float* __restrict__ out,
             int L, int C, int wstride)
{
    const int b = blockIdx.x;
    const int t = threadIdx.x;
    const int Lv = L >> 2;

    __shared__ float sW0[20], sW1[20], sW2[20];
    if (t < 20) {
        sW0[t] = __ldg(&W[0 * wstride + t]);
        sW1[t] = __ldg(&W[1 * wstride + t]);
        sW2[t] = __ldg(&W[2 * wstride + t]);
    }
    __syncthreads();

    const float4* xb = (const float4*)(x + (size_t)b * (size_t)C * (size_t)L);
    float contrib = 0.f, cnt = 0.f;

    for (int i = t; i < Lv; i += 128) {
        float4 sl0 = __ldg((const float4*)&g_slog[0 * L] + i);
        float4 sl1 = __ldg((const float4*)&g_slog[1 * L] + i);
        float4 sl2 = __ldg((const float4*)&g_slog[2 * L] + i);
        float4 h0  = __ldg((const float4*)&ss_hmm[0 * L] + i);
        float4 h1  = __ldg((const float4*)&ss_hmm[1 * L] + i);
        float4 h2  = __ldg((const float4*)&ss_hmm[2 * L] + i);

        float4 v0 = __ldcs(&xb[i]);
        float x0[4] = {v0.x, v0.y, v0.z, v0.w};
        float mx[4] = {-INFINITY, -INFINITY, -INFINITY, -INFINITY};
        float a0[4] = {0.f, 0.f, 0.f, 0.f};
        float a1[4] = {0.f, 0.f, 0.f, 0.f};
        float a2[4] = {0.f, 0.f, 0.f, 0.f};

        for (int c = 1; c < C; ++c) {
            float4 v = __ldcs(&xb[c * Lv + i]);
            float vv[4] = {v.x, v.y, v.z, v.w};
            float w0 = sW0[c - 1], w1 = sW1[c - 1], w2 = sW2[c - 1];
            #pragma unroll
            for (int j = 0; j < 4; ++j) {
                mx[j] = fmaxf(mx[j], vv[j]);
                a0[j] = fmaf(w0, vv[j], a0[j]);
                a1[j] = fmaf(w1, vv[j], a1[j]);
                a2[j] = fmaf(w2, vv[j], a2[j]);
            }
        }

        float sla0[4] = {sl0.x, sl0.y, sl0.z, sl0.w};
        float sla1[4] = {sl1.x, sl1.y, sl1.z, sl1.w};
        float sla2[4] = {sl2.x, sl2.y, sl2.z, sl2.w};
        float ha0[4]  = {h0.x, h0.y, h0.z, h0.w};
        float ha1[4]  = {h1.x, h1.y, h1.z, h1.w};
        float ha2[4]  = {h2.x, h2.y, h2.z, h2.w};

        #pragma unroll
        for (int j = 0; j < 4; ++j) {
            float e0 = __expf(a0[j] + sla0[j]);
            float e1 = __expf(a1[j] + sla1[j]);
            float e2 = __expf(a2[j] + sla2[j]);
            float num = ha0[j] * e0 + ha1[j] * e1 + ha2[j] * e2;
            float den = e0 + e1 + e2;
            bool m = mx[j] > x0[j];
            contrib += m ? __fdividef(num, den) : 0.f;
            cnt     += m ? 1.f : 0.f;
        }
    }

    #pragma unroll
    for (int off = 16; off > 0; off >>= 1) {
        contrib += __shfl_down_sync(0xffffffffu, contrib, off);
        cnt     += __shfl_down_sync(0xffffffffu, cnt, off);
    }
    __shared__ float rs[2][4];
    if ((t & 31) == 0) { rs[0][t >> 5] = contrib; rs[1][t >> 5] = cnt; }
    __syncthreads();
    if (t == 0) {
        float s = rs[0][0] + rs[0][1] + rs[0][2] + rs[0][3];
        float c = rs[1][0] + rs[1][1] + rs[1][2] + rs[1][3];
        out[b] = logf(s / c);
    }
}

__global__ void qpml_kernel_scalar(const float* __restrict__ x,
                                   const float* __restrict__ ss_hmm,
                                   const float* __restrict__ W,
                                   float* __restrict__ out,
                                   int L, int C, int wstride)
{
    const int b = blockIdx.x;
    const int t = threadIdx.x;
    const float* xb = x + (size_t)b * (size_t)C * (size_t)L;

    float contrib = 0.f, cnt = 0.f;
    for (int l = t; l < L; l += blockDim.x) {
        float x0 = xb[l];
        float mx = -INFINITY;
        float a0 = 0.f, a1 = 0.f, a2 = 0.f;
        for (int c = 1; c < C; ++c) {
            float v = xb[c * L + l];
            mx = fmaxf(mx, v);
            a0 = fmaf(W[0 * wstride + c - 1], v, a0);
            a1 = fmaf(W[1 * wstride + c - 1], v, a1);
            a2 = fmaf(W[2 * wstride + c - 1], v, a2);
        }
        float e0 = __expf(a0 + g_slog[0 * L + l]);
        float e1 = __expf(a1 + g_slog[1 * L + l]);
        float e2 = __expf(a2 + g_slog[2 * L + l]);
        float num = ss_hmm[0 * L + l] * e0 + ss_hmm[1 * L + l] * e1
                  + ss_hmm[2 * L + l] * e2;
        if (mx > x0) { contrib += num / (e0 + e1 + e2); cnt += 1.f; }
    }
    #pragma unroll
    for (int off = 16; off > 0; off >>= 1) {
        contrib += __shfl_down_sync(0xffffffffu, contrib, off);
        cnt     += __shfl_down_sync(0xffffffffu, cnt, off);
    }
    __shared__ float rs[2][32];
    int nw = (blockDim.x + 31) >> 5;
    if ((t & 31) == 0) { rs[0][t >> 5] = contrib; rs[1][t >> 5] = cnt; }
    __syncthreads();
    if (t == 0) {
        float s = 0.f, c = 0.f;
        for (int w = 0; w < nw; ++w) { s += rs[0][w]; c += rs[1][w]; }
        out[b] = logf(s / c);
    }
}

extern "C" void kernel_launch(void* const* d_in, const int* in_sizes, int n_in,
                              void* d_out, int out_size)
{
    const float* x       = (const float*)d_in[0];   // [B, 21, L]
    const float* seq_hmm = (const float*)d_in[1];   // [H, L]
    const float* ss_hmm  = (const float*)d_in[2];   // [3, L]
    const float* W       = (const float*)d_in[3];   // [3, 20+H]
    const float* bvec    = (const float*)d_in[4];   // [3]
    float* out = (float*)d_out;

    const int B       = out_size;                   // 4096
    const int L       = in_sizes[2] / 3;            // 512
    const int H       = in_sizes[1] / L;            // 30
    const int C       = in_sizes[0] / (B * L);      // 21
    const int wstride = in_sizes[3] / 3;            // 20 + H = 50

    if (C == FC && L == FL && H <= 44 && wstride <= 64) {
        cudaFuncSetAttribute(qpml_persist,
                             cudaFuncAttributeMaxDynamicSharedMemorySize,
                             SMEM_DYN);
        int grid = (B < GRIDP) ? B : GRIDP;
        qpml_persist<<<grid, NT, SMEM_DYN>>>(x, seq_hmm, ss_hmm, W, bvec,
                                             out, B, H, wstride);
    } else if ((L & 3) == 0 && L <= MAX_L) {
        slog_kernel<<<(L + 255) / 256, 256>>>(seq_hmm, W, bvec, L, H, wstride);
        qpml_generic<<<B, 128>>>(x, ss_hmm, W, out, L, C, wstride);
    } else {
        slog_kernel<<<(L + 255) / 256, 256>>>(seq_hmm, W, bvec, L, H, wstride);
        qpml_kernel_scalar<<<B, 128>>>(x, ss_hmm, W, out, L, C, wstride);
    }
}

// round 10
// speedup vs baseline: 1.0113x; 1.0113x over previous
#include <cuda_runtime.h>
#include <math.h>
#include <stdint.h>

// ---------------------------------------------------------------------------
// QuickPatternMatchingLoss
//   out[b] = log( (1/ls) * sum_{l: mask} sum_o ss_hmm[o,l] *
//                 softmax_o( W[:, :20] . x[b,1:,l] + slog[:,l] ) )
//   slog[o,l] = b[o] + sum_h W[o,20+h] * seq_hmm[h,l]
//   mask[b,l] = ( max_{c>=1} x[b,c,l] > x[b,0,l] )
//
// R10: persistent double-buffered TMA; 256 threads, float2 per thread.
// R8 (128thr/float4) was serial-latency-bound at 2 warps/SMSP; R9
// (512thr/scalar) quadrupled LDS instrs + 16-warp BAR coupling. This is the
// interpolation: 4 warps/SMSP, LDS.64 density, rebased softmax (e0==1),
// ONE barrier per row (parity rs), refill issued right after the barrier
// before the final combine.
// ---------------------------------------------------------------------------

#define MAX_L 2048
__device__ float g_slog[3 * MAX_L];   // fallback path scratch

#define FL 512
#define FC 21
#define FL2 (FL / 2)                   // 256 float2 per channel row
#define ROW_BYTES (FC * FL * 4)        // 43008
#define GRIDP 304                      // 2 CTAs/SM x 152 SMs
#define SMEM_DYN (2 * ROW_BYTES)       // 86016
#define NT 256                         // threads per CTA (fast path)
#define NW (NT / 32)                   // 8 warps

__device__ __forceinline__ uint32_t smem_u32(const void* p) {
    uint32_t a;
    asm("{ .reg .u64 t; cvta.to.shared.u64 t, %1; cvt.u32.u64 %0, t; }"
        : "=r"(a) : "l"(p));
    return a;
}
__device__ __forceinline__ void mbar_init(uint32_t mbar, uint32_t count) {
    asm volatile("mbarrier.init.shared.b64 [%0], %1;" :: "r"(mbar), "r"(count) : "memory");
}
__device__ __forceinline__ void mbar_expect_tx(uint32_t mbar, uint32_t bytes) {
    asm volatile("mbarrier.arrive.expect_tx.shared.b64 _, [%0], %1;"
                 :: "r"(mbar), "r"(bytes) : "memory");
}
__device__ __forceinline__ void bulk_g2s(uint32_t dst, const void* src,
                                         uint32_t bytes, uint32_t mbar) {
    asm volatile(
        "cp.async.bulk.shared::cta.global.mbarrier::complete_tx::bytes "
        "[%0], [%1], %2, [%3];"
        :: "r"(dst), "l"(src), "r"(bytes), "r"(mbar) : "memory");
}
__device__ __forceinline__ void mbar_wait(uint32_t mbar, uint32_t parity) {
    uint32_t done;
    asm volatile(
        "{\n\t.reg .pred p;\n\t"
        "mbarrier.try_wait.parity.acquire.cta.shared::cta.b64 p, [%1], %2;\n\t"
        "selp.b32 %0, 1, 0, p;\n\t}"
        : "=r"(done) : "r"(mbar), "r"(parity) : "memory");
    if (!done) {
        asm volatile(
            "{\n\t.reg .pred P1;\n\t"
            "WAIT_LOOP_%=:\n\t"
            "mbarrier.try_wait.parity.acquire.cta.shared::cta.b64 P1, [%0], %1, 0x989680;\n\t"
            "@P1 bra.uni WAIT_DONE_%=;\n\t"
            "bra.uni WAIT_LOOP_%=;\n\t"
            "WAIT_DONE_%=:\n\t}"
            :: "r"(mbar), "r"(parity) : "memory");
    }
}

// ---- persistent double-buffered fast path -----------------------------------
__global__ void __launch_bounds__(NT, 2)
qpml_persist(const float* __restrict__ x,
             const float* __restrict__ seq_hmm,
             const float* __restrict__ ss_hmm,
             const float* __restrict__ W,
             const float* __restrict__ bvec,
             float* __restrict__ out,
             int B, int H, int wstride)
{
    extern __shared__ __align__(16) float dyn[];
    const float2* buf2[2] = { (const float2*)dyn,
                              (const float2*)(dyn + FC * FL) };

    __shared__ float sW0[64], sW1[64], sW2[64];
    __shared__ __align__(8) unsigned long long mb[2];
    __shared__ float rs0[2][NW], rs1[2][NW];

    const int t = threadIdx.x;
    const int warp = t >> 5, lane = t & 31;
    const int cta = blockIdx.x;
    const int G = gridDim.x;

    if (t < 2) mbar_init(smem_u32(&mb[t]), 1);
    if (t < wstride && t < 64) {
        sW0[t] = __ldg(&W[0 * wstride + t]);
        sW1[t] = __ldg(&W[1 * wstride + t]);
        sW2[t] = __ldg(&W[2 * wstride + t]);
    }
    __syncthreads();

    const uint32_t buf_sm[2] = { smem_u32(buf2[0]), smem_u32(buf2[1]) };
    const uint32_t mbs[2]    = { smem_u32(&mb[0]), smem_u32(&mb[1]) };

    // prefill both buffers
    if (t == 0) {
        if (cta < B) {
            mbar_expect_tx(mbs[0], ROW_BYTES);
            bulk_g2s(buf_sm[0], (const char*)x + (size_t)cta * ROW_BYTES,
                     ROW_BYTES, mbs[0]);
        }
        if (cta + G < B) {
            mbar_expect_tx(mbs[1], ROW_BYTES);
            bulk_g2s(buf_sm[1], (const char*)x + (size_t)(cta + G) * ROW_BYTES,
                     ROW_BYTES, mbs[1]);
        }
    }

    // per-thread tables for columns 2t, 2t+1 (computed under the first fill)
    float2 d10, d20, h0c, h1c, h2c;
    {
        float bb0 = __ldg(&bvec[0]), bb1 = __ldg(&bvec[1]), bb2 = __ldg(&bvec[2]);
        float2 s0 = make_float2(bb0, bb0);
        float2 s1 = make_float2(bb1, bb1);
        float2 s2 = make_float2(bb2, bb2);
        for (int h = 0; h < H; ++h) {
            float2 v = __ldg((const float2*)seq_hmm + h * FL2 + t);
            float w0 = sW0[20 + h], w1 = sW1[20 + h], w2 = sW2[20 + h];
            s0.x = fmaf(w0, v.x, s0.x); s0.y = fmaf(w0, v.y, s0.y);
            s1.x = fmaf(w1, v.x, s1.x); s1.y = fmaf(w1, v.y, s1.y);
            s2.x = fmaf(w2, v.x, s2.x); s2.y = fmaf(w2, v.y, s2.y);
        }
        d10 = make_float2(s1.x - s0.x, s1.y - s0.y);
        d20 = make_float2(s2.x - s0.x, s2.y - s0.y);
        h0c = __ldg((const float2*)ss_hmm + 0 * FL2 + t);
        h1c = __ldg((const float2*)ss_hmm + 1 * FL2 + t);
        h2c = __ldg((const float2*)ss_hmm + 2 * FL2 + t);
    }

    int ph[2] = {0, 0};
    int it = 0;
    for (int r = cta; r < B; r += G, ++it) {
        const int k = it & 1;
        const float2* bk = buf2[k];

        mbar_wait(mbs[k], ph[k]);
        ph[k] ^= 1;

        float2 v0 = bk[t];                 // gap channel, cols 2t/2t+1
        float mxx = -INFINITY, mxy = -INFINITY;
        float a0x = 0.f, a0y = 0.f;
        float a1x = 0.f, a1y = 0.f;
        float a2x = 0.f, a2y = 0.f;

        #pragma unroll
        for (int c = 1; c < FC; ++c) {
            float2 v = bk[c * FL2 + t];
            float w0 = sW0[c - 1], w1 = sW1[c - 1], w2 = sW2[c - 1];
            mxx = fmaxf(mxx, v.x);        mxy = fmaxf(mxy, v.y);
            a0x = fmaf(w0, v.x, a0x);     a0y = fmaf(w0, v.y, a0y);
            a1x = fmaf(w1, v.x, a1x);     a1y = fmaf(w1, v.y, a1y);
            a2x = fmaf(w2, v.x, a2x);     a2y = fmaf(w2, v.y, a2y);
        }

        // rebased softmax: e0 == 1
        float e1x = __expf((a1x - a0x) + d10.x);
        float e2x = __expf((a2x - a0x) + d20.x);
        float e1y = __expf((a1y - a0y) + d10.y);
        float e2y = __expf((a2y - a0y) + d20.y);
        float numx = fmaf(h2c.x, e2x, fmaf(h1c.x, e1x, h0c.x));
        float denx = 1.f + e1x + e2x;
        float numy = fmaf(h2c.y, e2y, fmaf(h1c.y, e1y, h0c.y));
        float deny = 1.f + e1y + e2y;
        bool mxm = mxx > v0.x;
        bool mym = mxy > v0.y;
        float contrib = (mxm ? __fdividef(numx, denx) : 0.f)
                      + (mym ? __fdividef(numy, deny) : 0.f);
        float cnt = (mxm ? 1.f : 0.f) + (mym ? 1.f : 0.f);

        #pragma unroll
        for (int off = 16; off > 0; off >>= 1) {
            contrib += __shfl_down_sync(0xffffffffu, contrib, off);
            cnt     += __shfl_down_sync(0xffffffffu, cnt, off);
        }
        const int p = it & 1;
        if (lane == 0) { rs0[p][warp] = contrib; rs1[p][warp] = cnt; }

        __syncthreads();   // all reads of buf[k] done + rs visible

        // refill FIRST (restart the DRAM stream asap), then combine
        if (t == 0) {
            int rf = r + 2 * G;
            if (rf < B) {
                mbar_expect_tx(mbs[k], ROW_BYTES);
                bulk_g2s(buf_sm[k],
                         (const char*)x + (size_t)rf * ROW_BYTES,
                         ROW_BYTES, mbs[k]);
            }
        }
        if (warp == 0) {
            float s = (lane < NW) ? rs0[p][lane] : 0.f;
            float c = (lane < NW) ? rs1[p][lane] : 0.f;
            #pragma unroll
            for (int off = NW / 2; off > 0; off >>= 1) {
                s += __shfl_down_sync(0xffffffffu, s, off);
                c += __shfl_down_sync(0xffffffffu, c, off);
            }
            if (lane == 0) out[r] = logf(s / c);
        }
        // next iteration uses the other buffer/parity; rs[p] reuse is safe
        // because buf[k]'s next full-wait orders it behind this row's refill.
    }
}

// ---- fallback paths (non-512x21 shapes) --------------------------------------
__global__ void slog_kernel(const float* __restrict__ seq_hmm,
                            const float* __restrict__ W,
                            const float* __restrict__ bvec,
                            int L, int H, int wstride)
{
    int l = blockIdx.x * blockDim.x + threadIdx.x;
    if (l >= L) return;
    float s0 = bvec[0], s1 = bvec[1], s2 = bvec[2];
    for (int h = 0; h < H; ++h) {
        float v = __ldg(&seq_hmm[h * L + l]);
        s0 = fmaf(__ldg(&W[0 * wstride + 20 + h]), v, s0);
        s1 = fmaf(__ldg(&W[1 * wstride + 20 + h]), v, s1);
        s2 = fmaf(__ldg(&W[2 * wstride + 20 + h]), v, s2);
    }
    g_slog[0 * L + l] = s0;
    g_slog[1 * L + l] = s1;
    g_slog[2 * L + l] = s2;
}

__global__ void __launch_bounds__(128, 6)
qpml_generic(const float* __restrict__ x,
             const float* __restrict__ ss_hmm,
             const float* __restrict__ W,
             float* __restrict__ out,
             int L, int C, int wstride)
{
    const int b = blockIdx.x;
    const int t = threadIdx.x;
    const int Lv = L >> 2;

    __shared__ float sW0[20], sW1[20], sW2[20];
    if (t < 20) {
        sW0[t] = __ldg(&W[0 * wstride + t]);
        sW1[t] = __ldg(&W[1 * wstride + t]);
        sW2[t] = __ldg(&W[2 * wstride + t]);
    }
    __syncthreads();

    const float4* xb = (const float4*)(x + (size_t)b * (size_t)C * (size_t)L);
    float contrib = 0.f, cnt = 0.f;

    for (int i = t; i < Lv; i += 128) {
        float4 sl0 = __ldg((const float4*)&g_slog[0 * L] + i);
        float4 sl1 = __ldg((const float4*)&g_slog[1 * L] + i);
        float4 sl2 = __ldg((const float4*)&g_slog[2 * L] + i);
        float4 h0  = __ldg((const float4*)&ss_hmm[0 * L] + i);
        float4 h1  = __ldg((const float4*)&ss_hmm[1 * L] + i);
        float4 h2  = __ldg((const float4*)&ss_hmm[2 * L] + i);

        float4 v0 = __ldcs(&xb[i]);
        float x0[4] = {v0.x, v0.y, v0.z, v0.w};
        float mx[4] = {-INFINITY, -INFINITY, -INFINITY, -INFINITY};
        float a0[4] = {0.f, 0.f, 0.f, 0.f};
        float a1[4] = {0.f, 0.f, 0.f, 0.f};
        float a2[4] = {0.f, 0.f, 0.f, 0.f};

        for (int c = 1; c < C; ++c) {
            float4 v = __ldcs(&xb[c * Lv + i]);
            float vv[4] = {v.x, v.y, v.z, v.w};
            float w0 = sW0[c - 1], w1 = sW1[c - 1], w2 = sW2[c - 1];
            #pragma unroll
            for (int j = 0; j < 4; ++j) {
                mx[j] = fmaxf(mx[j], vv[j]);
                a0[j] = fmaf(w0, vv[j], a0[j]);
                a1[j] = fmaf(w1, vv[j], a1[j]);
                a2[j] = fmaf(w2, vv[j], a2[j]);
            }
        }

        float sla0[4] = {sl0.x, sl0.y, sl0.z, sl0.w};
        float sla1[4] = {sl1.x, sl1.y, sl1.z, sl1.w};
        float sla2[4] = {sl2.x, sl2.y, sl2.z, sl2.w};
        float ha0[4]  = {h0.x, h0.y, h0.z, h0.w};
        float ha1[4]  = {h1.x, h1.y, h1.z, h1.w};
        float ha2[4]  = {h2.x, h2.y, h2.z, h2.w};

        #pragma unroll
        for (int j = 0; j < 4; ++j) {
            float e0 = __expf(a0[j] + sla0[j]);
            float e1 = __expf(a1[j] + sla1[j]);
            float e2 = __expf(a2[j] + sla2[j]);
            float num = ha0[j] * e0 + ha1[j] * e1 + ha2[j] * e2;
            float den = e0 + e1 + e2;
            bool m = mx[j] > x0[j];
            contrib += m ? __fdividef(num, den) : 0.f;
            cnt     += m ? 1.f : 0.f;
        }
    }

    #pragma unroll
    for (int off = 16; off > 0; off >>= 1) {
        contrib += __shfl_down_sync(0xffffffffu, contrib, off);
        cnt     += __shfl_down_sync(0xffffffffu, cnt, off);
    }
    __shared__ float rs[2][4];
    if ((t & 31) == 0) { rs[0][t >> 5] = contrib; rs[1][t >> 5] = cnt; }
    __syncthreads();
    if (t == 0) {
        float s = rs[0][0] + rs[0][1] + rs[0][2] + rs[0][3];
        float c = rs[1][0] + rs[1][1] + rs[1][2] + rs[1][3];
        out[b] = logf(s / c);
    }
}

__global__ void qpml_kernel_scalar(const float* __restrict__ x,
                                   const float* __restrict__ ss_hmm,
                                   const float* __restrict__ W,
                                   float* __restrict__ out,
                                   int L, int C, int wstride)
{
    const int b = blockIdx.x;
    const int t = threadIdx.x;
    const float* xb = x + (size_t)b * (size_t)C * (size_t)L;

    float contrib = 0.f, cnt = 0.f;
    for (int l = t; l < L; l += blockDim.x) {
        float x0 = xb[l];
        float mx = -INFINITY;
        float a0 = 0.f, a1 = 0.f, a2 = 0.f;
        for (int c = 1; c < C; ++c) {
            float v = xb[c * L + l];
            mx = fmaxf(mx, v);
            a0 = fmaf(W[0 * wstride + c - 1], v, a0);
            a1 = fmaf(W[1 * wstride + c - 1], v, a1);
            a2 = fmaf(W[2 * wstride + c - 1], v, a2);
        }
        float e0 = __expf(a0 + g_slog[0 * L + l]);
        float e1 = __expf(a1 + g_slog[1 * L + l]);
        float e2 = __expf(a2 + g_slog[2 * L + l]);
        float num = ss_hmm[0 * L + l] * e0 + ss_hmm[1 * L + l] * e1
                  + ss_hmm[2 * L + l] * e2;
        if (mx > x0) { contrib += num / (e0 + e1 + e2); cnt += 1.f; }
    }
    #pragma unroll
    for (int off = 16; off > 0; off >>= 1) {
        contrib += __shfl_down_sync(0xffffffffu, contrib, off);
        cnt     += __shfl_down_sync(0xffffffffu, cnt, off);
    }
    __shared__ float rs[2][32];
    int nw = (blockDim.x + 31) >> 5;
    if ((t & 31) == 0) { rs[0][t >> 5] = contrib; rs[1][t >> 5] = cnt; }
    __syncthreads();
    if (t == 0) {
        float s = 0.f, c = 0.f;
        for (int w = 0; w < nw; ++w) { s += rs[0][w]; c += rs[1][w]; }
        out[b] = logf(s / c);
    }
}

extern "C" void kernel_launch(void* const* d_in, const int* in_sizes, int n_in,
                              void* d_out, int out_size)
{
    const float* x       = (const float*)d_in[0];   // [B, 21, L]
    const float* seq_hmm = (const float*)d_in[1];   // [H, L]
    const float* ss_hmm  = (const float*)d_in[2];   // [3, L]
    const float* W       = (const float*)d_in[3];   // [3, 20+H]
    const float* bvec    = (const float*)d_in[4];   // [3]
    float* out = (float*)d_out;

    const int B       = out_size;                   // 4096
    const int L       = in_sizes[2] / 3;            // 512
    const int H       = in_sizes[1] / L;            // 30
    const int C       = in_sizes[0] / (B * L);      // 21
    const int wstride = in_sizes[3] / 3;            // 20 + H = 50

    if (C == FC && L == FL && H <= 44 && wstride <= 64) {
        cudaFuncSetAttribute(qpml_persist,
                             cudaFuncAttributeMaxDynamicSharedMemorySize,
                             SMEM_DYN);
        int grid = (B < GRIDP) ? B : GRIDP;
        qpml_persist<<<grid, NT, SMEM_DYN>>>(x, seq_hmm, ss_hmm, W, bvec,
                                             out, B, H, wstride);
    } else if ((L & 3) == 0 && L <= MAX_L) {
        slog_kernel<<<(L + 255) / 256, 256>>>(seq_hmm, W, bvec, L, H, wstride);
        qpml_generic<<<B, 128>>>(x, ss_hmm, W, out, L, C, wstride);
    } else {
        slog_kernel<<<(L + 255) / 256, 256>>>(seq_hmm, W, bvec, L, H, wstride);
        qpml_kernel_scalar<<<B, 128>>>(x, ss_hmm, W, out, L, C, wstride);
    }
}